// round 1
// baseline (speedup 1.0000x reference)
#include <cuda_runtime.h>
#include <math.h>

#define NN 100000
#define EE 1600000
#define OUTD 64
#define IND 128

// ---- scratch (static __device__ arrays; no allocation allowed) ----
static __device__ float g_Wh[(size_t)NN * OUTD];      // 25.6 MB
static __device__ float g_asrc[NN * 4];
static __device__ float g_adst[NN * 4];
static __device__ float g_e[(size_t)EE * 4];          // 25.6 MB (logits, then exp)
static __device__ float g_den[NN * 4];
static __device__ unsigned g_maxbits;

__device__ __forceinline__ void red_add_v4(float* p, float4 v) {
    asm volatile("red.global.add.v4.f32 [%0], {%1,%2,%3,%4};"
                 :: "l"(p), "f"(v.x), "f"(v.y), "f"(v.z), "f"(v.w) : "memory");
}

__device__ __forceinline__ unsigned enc_f(float f) {
    unsigned u = __float_as_uint(f);
    return (u & 0x80000000u) ? ~u : (u | 0x80000000u);
}
__device__ __forceinline__ float dec_f(unsigned u) {
    int i = (u & 0x80000000u) ? (int)(u & 0x7fffffffu) : (int)~u;
    return __int_as_float(i);
}

// ---- K0: zero accumulators + output ----
__global__ void k_init(float* __restrict__ out) {
    int i = blockIdx.x * blockDim.x + threadIdx.x;
    int stride = gridDim.x * blockDim.x;
    for (int j = i; j < NN * OUTD; j += stride) out[j] = 0.f;
    for (int j = i; j < NN * 4; j += stride) g_den[j] = 0.f;
    if (i == 0) g_maxbits = 0u;  // below any real float's encoding
}

// ---- K1: Wh = x @ W_node^T ; a_src/a_dst per node ----
// one block of 64 threads per node; thread t computes Wh[n][t]
__global__ void __launch_bounds__(64) k_node(
    const float* __restrict__ x, const float* __restrict__ Wn,
    const float* __restrict__ att_s, const float* __restrict__ att_d) {
    __shared__ float xs[IND];
    int n = blockIdx.x;
    int t = threadIdx.x;
    const float4* xr = (const float4*)(x + (size_t)n * IND);
    if (t < 32) ((float4*)xs)[t] = xr[t];
    __syncthreads();
    const float4* wr = (const float4*)(Wn + (size_t)t * IND);
    float acc = 0.f;
#pragma unroll
    for (int j = 0; j < 32; j++) {
        float4 w = __ldg(wr + j);
        float4 xv = ((const float4*)xs)[j];
        acc += w.x * xv.x + w.y * xv.y + w.z * xv.z + w.w * xv.w;
    }
    g_Wh[(size_t)n * OUTD + t] = acc;
    // attention scalars: reduce Wh[h]*att over 16-lane groups
    float vs = acc * __ldg(att_s + t);
    float vd = acc * __ldg(att_d + t);
#pragma unroll
    for (int o = 8; o >= 1; o >>= 1) {
        vs += __shfl_xor_sync(0xffffffffu, vs, o);
        vd += __shfl_xor_sync(0xffffffffu, vd, o);
    }
    if ((t & 15) == 0) {
        int h = t >> 4;
        g_asrc[n * 4 + h] = vs;
        g_adst[n * 4 + h] = vd;
    }
}

// ---- K2: e = leaky_relu(a_src[s]+a_dst[d]+ea@We^T), track global max ----
__global__ void __launch_bounds__(256) k_edge_e(
    const int* __restrict__ ei, const float* __restrict__ ea,
    const float* __restrict__ We) {
    __shared__ float we[64];
    __shared__ float wmax[8];
    int t = threadIdx.x;
    if (t < 64) we[t] = We[t];
    __syncthreads();
    int i = blockIdx.x * 256 + t;
    float m = -1e30f;
    if (i < EE) {
        int s = ei[i];
        int d = ei[EE + i];
        float eav[16];
        const float4* er = (const float4*)(ea + (size_t)i * 16);
#pragma unroll
        for (int j = 0; j < 4; j++) ((float4*)eav)[j] = __ldg(er + j);
        float4 as = *(const float4*)(g_asrc + (size_t)s * 4);
        float4 ad = *(const float4*)(g_adst + (size_t)d * 4);
        float base[4] = {as.x + ad.x, as.y + ad.y, as.z + ad.z, as.w + ad.w};
        float4 ev;
        float* evp = (float*)&ev;
#pragma unroll
        for (int h = 0; h < 4; h++) {
            float dot = 0.f;
            const float* w = we + h * 16;
#pragma unroll
            for (int k = 0; k < 16; k++) dot += eav[k] * w[k];
            float v = base[h] + dot;
            v = (v > 0.f) ? v : 0.2f * v;  // leaky_relu, slope 0.2
            evp[h] = v;
            m = fmaxf(m, v);
        }
        *(float4*)(g_e + (size_t)i * 4) = ev;
    }
    // block max -> one atomic per block
#pragma unroll
    for (int o = 16; o >= 1; o >>= 1) m = fmaxf(m, __shfl_xor_sync(0xffffffffu, m, o));
    if ((t & 31) == 0) wmax[t >> 5] = m;
    __syncthreads();
    if (t < 8) {
        m = wmax[t];
#pragma unroll
        for (int o = 4; o >= 1; o >>= 1) m = fmaxf(m, __shfl_xor_sync(0xffu, m, o));
        if (t == 0) atomicMax(&g_maxbits, enc_f(m));
    }
}

// ---- K3: ex = exp(e - max); den[d] += ex ----
__global__ void __launch_bounds__(256) k_edge_den(const int* __restrict__ ei) {
    int i = blockIdx.x * 256 + threadIdx.x;
    if (i >= EE) return;
    float mx = dec_f(g_maxbits);
    float4 e = *(const float4*)(g_e + (size_t)i * 4);
    float4 ex = make_float4(expf(e.x - mx), expf(e.y - mx),
                            expf(e.z - mx), expf(e.w - mx));
    *(float4*)(g_e + (size_t)i * 4) = ex;
    int d = ei[EE + i];
    red_add_v4(g_den + (size_t)d * 4, ex);
}

// ---- K4: out[d] += Wh[s] * alpha ; 16 threads per edge (one float4 each) ----
__global__ void __launch_bounds__(256) k_scatter(const int* __restrict__ ei,
                                                 float* __restrict__ out) {
    int idx = blockIdx.x * 256 + threadIdx.x;
    if (idx >= EE * 16) return;
    int i = idx >> 4;
    int j = idx & 15;      // which float4 of the 64-dim row
    int h = j >> 2;        // head
    int s = __ldg(ei + i);
    int d = __ldg(ei + EE + i);
    float ex = __ldg(g_e + (size_t)i * 4 + h);
    float den = __ldg(g_den + (size_t)d * 4 + h);
    float alpha = ex / (den + 1e-9f);
    float4 w = *(const float4*)(g_Wh + (size_t)s * OUTD + j * 4);
    w.x *= alpha; w.y *= alpha; w.z *= alpha; w.w *= alpha;
    red_add_v4(out + (size_t)d * OUTD + j * 4, w);
}

// ---- K5: out = elu(out + bias) in place ----
__global__ void __launch_bounds__(256) k_final(float* __restrict__ out,
                                               const float* __restrict__ bias) {
    int i = blockIdx.x * 256 + threadIdx.x;
    if (i >= NN * OUTD) return;
    float v = out[i] + __ldg(bias + (i & 63));
    out[i] = (v > 0.f) ? v : expm1f(v);
}

extern "C" void kernel_launch(void* const* d_in, const int* in_sizes, int n_in,
                              void* d_out, int out_size) {
    const float* x     = (const float*)d_in[0];
    const int*   ei    = (const int*)d_in[1];
    const float* ea    = (const float*)d_in[2];
    const float* Wn    = (const float*)d_in[3];
    const float* We    = (const float*)d_in[4];
    const float* att_s = (const float*)d_in[5];
    const float* att_d = (const float*)d_in[6];
    const float* bias  = (const float*)d_in[7];
    float* out = (float*)d_out;

    k_init<<<2048, 256>>>(out);
    k_node<<<NN, 64>>>(x, Wn, att_s, att_d);
    int ebl = (EE + 255) / 256;
    k_edge_e<<<ebl, 256>>>(ei, ea, We);
    k_edge_den<<<ebl, 256>>>(ei);
    k_scatter<<<(EE * 16 + 255) / 256, 256>>>(ei, out);
    k_final<<<(NN * OUTD + 255) / 256, 256>>>(out, bias);
}

// round 2
// speedup vs baseline: 1.0497x; 1.0497x over previous
#include <cuda_runtime.h>
#include <math.h>

#define NN 100000
#define EE 1600000
#define OUTD 64
#define IND 128
#define NBLK ((NN + 255) / 256)   // 391 scan blocks

// ---- scratch (static __device__ arrays; no allocation allowed) ----
static __device__ float g_Wh[(size_t)NN * OUTD];        // 25.6 MB
static __device__ float g_asrc[NN * 4];
static __device__ float g_adst[NN * 4];
static __device__ float g_e[(size_t)EE * 4];            // 25.6 MB logits
static __device__ int   g_count[NN];
static __device__ int   g_rowstart[NN];
static __device__ int   g_cursor[NN];
static __device__ int   g_bsum[NBLK];
static __device__ int   g_bsumx[NBLK];
static __device__ int   g_csr_src[EE];                  // 6.4 MB
static __device__ float g_csr_ex[(size_t)EE * 4];       // 25.6 MB
static __device__ unsigned g_maxbits;

__device__ __forceinline__ unsigned enc_f(float f) {
    unsigned u = __float_as_uint(f);
    return (u & 0x80000000u) ? ~u : (u | 0x80000000u);
}
__device__ __forceinline__ float dec_f(unsigned u) {
    int i = (u & 0x80000000u) ? (int)(u & 0x7fffffffu) : (int)~u;
    return __int_as_float(i);
}

// ---- K0: zero counts ----
__global__ void k_init() {
    int i = blockIdx.x * blockDim.x + threadIdx.x;
    if (i < NN) g_count[i] = 0;
    if (i == 0) g_maxbits = 0u;
}

// ---- K1: Wh = x @ W_node^T ; a_src/a_dst per node ----
__global__ void __launch_bounds__(64) k_node(
    const float* __restrict__ x, const float* __restrict__ Wn,
    const float* __restrict__ att_s, const float* __restrict__ att_d) {
    __shared__ float xs[IND];
    int n = blockIdx.x;
    int t = threadIdx.x;
    const float4* xr = (const float4*)(x + (size_t)n * IND);
    if (t < 32) ((float4*)xs)[t] = xr[t];
    __syncthreads();
    const float4* wr = (const float4*)(Wn + (size_t)t * IND);
    float acc = 0.f;
#pragma unroll
    for (int j = 0; j < 32; j++) {
        float4 w = __ldg(wr + j);
        float4 xv = ((const float4*)xs)[j];
        acc += w.x * xv.x + w.y * xv.y + w.z * xv.z + w.w * xv.w;
    }
    g_Wh[(size_t)n * OUTD + t] = acc;
    float vs = acc * __ldg(att_s + t);
    float vd = acc * __ldg(att_d + t);
#pragma unroll
    for (int o = 8; o >= 1; o >>= 1) {
        vs += __shfl_xor_sync(0xffffffffu, vs, o);
        vd += __shfl_xor_sync(0xffffffffu, vd, o);
    }
    if ((t & 15) == 0) {
        int h = t >> 4;
        g_asrc[n * 4 + h] = vs;
        g_adst[n * 4 + h] = vd;
    }
}

// ---- K2: e = leaky_relu(...), global max, degree histogram ----
__global__ void __launch_bounds__(256) k_edge_e(
    const int* __restrict__ ei, const float* __restrict__ ea,
    const float* __restrict__ We) {
    __shared__ float we[64];
    __shared__ float wmax[8];
    int t = threadIdx.x;
    if (t < 64) we[t] = We[t];
    __syncthreads();
    int i = blockIdx.x * 256 + t;
    float m = -1e30f;
    if (i < EE) {
        int s = ei[i];
        int d = ei[EE + i];
        float eav[16];
        const float4* er = (const float4*)(ea + (size_t)i * 16);
#pragma unroll
        for (int j = 0; j < 4; j++) ((float4*)eav)[j] = __ldg(er + j);
        float4 as = *(const float4*)(g_asrc + (size_t)s * 4);
        float4 ad = *(const float4*)(g_adst + (size_t)d * 4);
        float base[4] = {as.x + ad.x, as.y + ad.y, as.z + ad.z, as.w + ad.w};
        float4 ev;
        float* evp = (float*)&ev;
#pragma unroll
        for (int h = 0; h < 4; h++) {
            float dot = 0.f;
            const float* w = we + h * 16;
#pragma unroll
            for (int k = 0; k < 16; k++) dot += eav[k] * w[k];
            float v = base[h] + dot;
            v = (v > 0.f) ? v : 0.2f * v;
            evp[h] = v;
            m = fmaxf(m, v);
        }
        *(float4*)(g_e + (size_t)i * 4) = ev;
        atomicAdd(&g_count[d], 1);
    }
#pragma unroll
    for (int o = 16; o >= 1; o >>= 1) m = fmaxf(m, __shfl_xor_sync(0xffffffffu, m, o));
    if ((t & 31) == 0) wmax[t >> 5] = m;
    __syncthreads();
    if (t < 8) {
        m = wmax[t];
#pragma unroll
        for (int o = 4; o >= 1; o >>= 1) m = fmaxf(m, __shfl_xor_sync(0xffu, m, o));
        if (t == 0) atomicMax(&g_maxbits, enc_f(m));
    }
}

// ---- scan pass 1: per-block sums of counts ----
__global__ void __launch_bounds__(256) k_scan_bsum() {
    __shared__ int ws[8];
    int i = blockIdx.x * 256 + threadIdx.x;
    int c = (i < NN) ? g_count[i] : 0;
#pragma unroll
    for (int o = 16; o >= 1; o >>= 1) c += __shfl_xor_sync(0xffffffffu, c, o);
    if ((threadIdx.x & 31) == 0) ws[threadIdx.x >> 5] = c;
    __syncthreads();
    if (threadIdx.x < 8) {
        c = ws[threadIdx.x];
#pragma unroll
        for (int o = 4; o >= 1; o >>= 1) c += __shfl_xor_sync(0xffu, c, o);
        if (threadIdx.x == 0) g_bsum[blockIdx.x] = c;
    }
}

// ---- scan pass 2: exclusive scan of block sums (single block) ----
__global__ void __launch_bounds__(512) k_scan_top() {
    __shared__ int sh[512];
    int t = threadIdx.x;
    int v = (t < NBLK) ? g_bsum[t] : 0;
    sh[t] = v;
    __syncthreads();
#pragma unroll
    for (int o = 1; o < 512; o <<= 1) {
        int add = (t >= o) ? sh[t - o] : 0;
        __syncthreads();
        sh[t] += add;
        __syncthreads();
    }
    if (t < NBLK) g_bsumx[t] = sh[t] - v;   // exclusive
}

// ---- scan pass 3: block exclusive scan + offset -> rowstart, cursor ----
__global__ void __launch_bounds__(256) k_scan_fin() {
    __shared__ int sh[256];
    int t = threadIdx.x;
    int i = blockIdx.x * 256 + t;
    int c = (i < NN) ? g_count[i] : 0;
    sh[t] = c;
    __syncthreads();
#pragma unroll
    for (int o = 1; o < 256; o <<= 1) {
        int add = (t >= o) ? sh[t - o] : 0;
        __syncthreads();
        sh[t] += add;
        __syncthreads();
    }
    if (i < NN) {
        int start = sh[t] - c + g_bsumx[blockIdx.x];
        g_rowstart[i] = start;
        g_cursor[i] = start;
    }
}

// ---- K3: exp + CSR bucket-scatter of (src, ex4) ----
__global__ void __launch_bounds__(256) k_csr(const int* __restrict__ ei) {
    int i = blockIdx.x * 256 + threadIdx.x;
    if (i >= EE) return;
    float mx = dec_f(g_maxbits);
    int s = __ldg(ei + i);
    int d = __ldg(ei + EE + i);
    float4 e = *(const float4*)(g_e + (size_t)i * 4);
    float4 ex = make_float4(expf(e.x - mx), expf(e.y - mx),
                            expf(e.z - mx), expf(e.w - mx));
    int pos = atomicAdd(&g_cursor[d], 1);
    g_csr_src[pos] = s;
    *(float4*)(g_csr_ex + (size_t)pos * 4) = ex;
}

// ---- K4: per-node gather-aggregate, fused bias + ELU ----
__global__ void __launch_bounds__(64) k_agg(float* __restrict__ out,
                                            const float* __restrict__ bias) {
    __shared__ int sh_src[64];
    __shared__ float sh_ex[64 * 4];
    int n = blockIdx.x;
    int t = threadIdx.x;
    int h = t >> 4;
    int cnt = g_count[n];
    int start = g_rowstart[n];
    float acc = 0.f, den = 0.f;
    for (int j0 = 0; j0 < cnt; j0 += 64) {
        int m = min(64, cnt - j0);
        __syncthreads();
        if (t < m) {
            sh_src[t] = __ldg(g_csr_src + start + j0 + t);
            ((float4*)sh_ex)[t] = *(const float4*)(g_csr_ex + (size_t)(start + j0 + t) * 4);
        }
        __syncthreads();
        for (int j = 0; j < m; j++) {
            float ex = sh_ex[j * 4 + h];
            den += ex;
            acc += ex * __ldg(g_Wh + (size_t)sh_src[j] * OUTD + t);
        }
    }
    float v = acc / (den + 1e-9f) + __ldg(bias + t);
    out[(size_t)n * OUTD + t] = (v > 0.f) ? v : expm1f(v);
}

extern "C" void kernel_launch(void* const* d_in, const int* in_sizes, int n_in,
                              void* d_out, int out_size) {
    const float* x     = (const float*)d_in[0];
    const int*   ei    = (const int*)d_in[1];
    const float* ea    = (const float*)d_in[2];
    const float* Wn    = (const float*)d_in[3];
    const float* We    = (const float*)d_in[4];
    const float* att_s = (const float*)d_in[5];
    const float* att_d = (const float*)d_in[6];
    const float* bias  = (const float*)d_in[7];
    float* out = (float*)d_out;

    k_init<<<NBLK, 256>>>();
    k_node<<<NN, 64>>>(x, Wn, att_s, att_d);
    int ebl = (EE + 255) / 256;
    k_edge_e<<<ebl, 256>>>(ei, ea, We);
    k_scan_bsum<<<NBLK, 256>>>();
    k_scan_top<<<1, 512>>>();
    k_scan_fin<<<NBLK, 256>>>();
    k_csr<<<ebl, 256>>>(ei);
    k_agg<<<NN, 64>>>(out, bias);
}

// round 3
// speedup vs baseline: 2.5277x; 2.4080x over previous
#include <cuda_runtime.h>
#include <math.h>

#define NN 100000
#define EE 1600000
#define OUTD 64
#define IND 128
#define NBLK ((NN + 255) / 256)   // 391 scan blocks

// ---- scratch (static __device__ arrays; no allocation allowed) ----
static __device__ float g_Wh[(size_t)NN * OUTD];        // 25.6 MB
static __device__ float g_asrc[NN * 4];
static __device__ float g_adst[NN * 4];
static __device__ float g_e[(size_t)EE * 4];            // 25.6 MB logits
static __device__ int   g_count[NN];
static __device__ int   g_rowstart[NN];
static __device__ int   g_cursor[NN];
static __device__ int   g_bsum[NBLK];
static __device__ int   g_bsumx[NBLK];
static __device__ int   g_csr_src[EE];                  // 6.4 MB
static __device__ float g_csr_ex[(size_t)EE * 4];       // 25.6 MB
static __device__ unsigned g_maxbits;

__device__ __forceinline__ unsigned enc_f(float f) {
    unsigned u = __float_as_uint(f);
    return (u & 0x80000000u) ? ~u : (u | 0x80000000u);
}
__device__ __forceinline__ float dec_f(unsigned u) {
    int i = (u & 0x80000000u) ? (int)(u & 0x7fffffffu) : (int)~u;
    return __int_as_float(i);
}
__device__ __forceinline__ float dot4(float4 a, float4 b) {
    return a.x * b.x + a.y * b.y + a.z * b.z + a.w * b.w;
}

// ---- K0: zero counts ----
__global__ void k_init() {
    int i = blockIdx.x * blockDim.x + threadIdx.x;
    if (i < NN) g_count[i] = 0;
    if (i == 0) g_maxbits = 0u;
}

// ---- K1: register-blocked GEMM Wh = x @ Wn^T, fused a_src/a_dst ----
// block = 256 threads -> 64 nodes x 64 cols. Thread (tx,ty): tx=t&15, ty=t>>4.
// Thread computes nodes n0+ty*4+i (i=0..3), cols tx+16j (j=0..3). head == j.
__global__ void __launch_bounds__(256) k_node(
    const float* __restrict__ x, const float* __restrict__ Wn,
    const float* __restrict__ att_s, const float* __restrict__ att_d) {
    int n0 = blockIdx.x * 64;
    int t = threadIdx.x;
    int tx = t & 15, ty = t >> 4;

    int node[4];
    const float4* xp[4];
#pragma unroll
    for (int i = 0; i < 4; i++) {
        node[i] = n0 + ty * 4 + i;
        int nc = (node[i] < NN) ? node[i] : (NN - 1);
        xp[i] = (const float4*)x + (size_t)nc * 32;
    }
    const float4* wp0 = (const float4*)Wn + (size_t)(tx) * 32;
    const float4* wp1 = (const float4*)Wn + (size_t)(tx + 16) * 32;
    const float4* wp2 = (const float4*)Wn + (size_t)(tx + 32) * 32;
    const float4* wp3 = (const float4*)Wn + (size_t)(tx + 48) * 32;

    float acc[4][4];
#pragma unroll
    for (int i = 0; i < 4; i++)
#pragma unroll
        for (int j = 0; j < 4; j++) acc[i][j] = 0.f;

#pragma unroll 8
    for (int kk = 0; kk < 32; kk++) {
        float4 b0 = __ldg(wp0 + kk);
        float4 b1 = __ldg(wp1 + kk);
        float4 b2 = __ldg(wp2 + kk);
        float4 b3 = __ldg(wp3 + kk);
#pragma unroll
        for (int i = 0; i < 4; i++) {
            float4 a = __ldg(xp[i] + kk);
            acc[i][0] += dot4(a, b0);
            acc[i][1] += dot4(a, b1);
            acc[i][2] += dot4(a, b2);
            acc[i][3] += dot4(a, b3);
        }
    }

    // attention partials: col = 16j + tx, head = j
    float ats[4], atd[4];
#pragma unroll
    for (int j = 0; j < 4; j++) {
        ats[j] = __ldg(att_s + 16 * j + tx);
        atd[j] = __ldg(att_d + 16 * j + tx);
    }
#pragma unroll
    for (int i = 0; i < 4; i++) {
        float4 ps, pd;
        float* psp = (float*)&ps;
        float* pdp = (float*)&pd;
#pragma unroll
        for (int j = 0; j < 4; j++) {
            psp[j] = acc[i][j] * ats[j];
            pdp[j] = acc[i][j] * atd[j];
        }
        // reduce over 16 lanes (tx)
#pragma unroll
        for (int o = 8; o >= 1; o >>= 1) {
#pragma unroll
            for (int j = 0; j < 4; j++) {
                psp[j] += __shfl_xor_sync(0xffffffffu, psp[j], o);
                pdp[j] += __shfl_xor_sync(0xffffffffu, pdp[j], o);
            }
        }
        if (tx == 0 && node[i] < NN) {
            *(float4*)(g_asrc + (size_t)node[i] * 4) = ps;
            *(float4*)(g_adst + (size_t)node[i] * 4) = pd;
        }
    }

    // store Wh
#pragma unroll
    for (int i = 0; i < 4; i++) {
        if (node[i] < NN) {
            float* o = g_Wh + (size_t)node[i] * OUTD + tx;
#pragma unroll
            for (int j = 0; j < 4; j++) o[16 * j] = acc[i][j];
        }
    }
}

// ---- K2: e = leaky_relu(...), global max, degree histogram ----
__global__ void __launch_bounds__(256) k_edge_e(
    const int* __restrict__ ei, const float* __restrict__ ea,
    const float* __restrict__ We) {
    __shared__ float we[64];
    __shared__ float wmax[8];
    int t = threadIdx.x;
    if (t < 64) we[t] = We[t];
    __syncthreads();
    int i = blockIdx.x * 256 + t;
    float m = -1e30f;
    if (i < EE) {
        int s = ei[i];
        int d = ei[EE + i];
        float eav[16];
        const float4* er = (const float4*)(ea + (size_t)i * 16);
#pragma unroll
        for (int j = 0; j < 4; j++) ((float4*)eav)[j] = __ldg(er + j);
        float4 as = *(const float4*)(g_asrc + (size_t)s * 4);
        float4 ad = *(const float4*)(g_adst + (size_t)d * 4);
        float base[4] = {as.x + ad.x, as.y + ad.y, as.z + ad.z, as.w + ad.w};
        float4 ev;
        float* evp = (float*)&ev;
#pragma unroll
        for (int h = 0; h < 4; h++) {
            float dot = 0.f;
            const float* w = we + h * 16;
#pragma unroll
            for (int k = 0; k < 16; k++) dot += eav[k] * w[k];
            float v = base[h] + dot;
            v = (v > 0.f) ? v : 0.2f * v;
            evp[h] = v;
            m = fmaxf(m, v);
        }
        *(float4*)(g_e + (size_t)i * 4) = ev;
        atomicAdd(&g_count[d], 1);
    }
#pragma unroll
    for (int o = 16; o >= 1; o >>= 1) m = fmaxf(m, __shfl_xor_sync(0xffffffffu, m, o));
    if ((t & 31) == 0) wmax[t >> 5] = m;
    __syncthreads();
    if (t < 8) {
        m = wmax[t];
#pragma unroll
        for (int o = 4; o >= 1; o >>= 1) m = fmaxf(m, __shfl_xor_sync(0xffu, m, o));
        if (t == 0) atomicMax(&g_maxbits, enc_f(m));
    }
}

// ---- scan pass 1: per-block sums of counts ----
__global__ void __launch_bounds__(256) k_scan_bsum() {
    __shared__ int ws[8];
    int i = blockIdx.x * 256 + threadIdx.x;
    int c = (i < NN) ? g_count[i] : 0;
#pragma unroll
    for (int o = 16; o >= 1; o >>= 1) c += __shfl_xor_sync(0xffffffffu, c, o);
    if ((threadIdx.x & 31) == 0) ws[threadIdx.x >> 5] = c;
    __syncthreads();
    if (threadIdx.x < 8) {
        c = ws[threadIdx.x];
#pragma unroll
        for (int o = 4; o >= 1; o >>= 1) c += __shfl_xor_sync(0xffu, c, o);
        if (threadIdx.x == 0) g_bsum[blockIdx.x] = c;
    }
}

// ---- scan pass 2: exclusive scan of block sums (single block) ----
__global__ void __launch_bounds__(512) k_scan_top() {
    __shared__ int sh[512];
    int t = threadIdx.x;
    int v = (t < NBLK) ? g_bsum[t] : 0;
    sh[t] = v;
    __syncthreads();
#pragma unroll
    for (int o = 1; o < 512; o <<= 1) {
        int add = (t >= o) ? sh[t - o] : 0;
        __syncthreads();
        sh[t] += add;
        __syncthreads();
    }
    if (t < NBLK) g_bsumx[t] = sh[t] - v;   // exclusive
}

// ---- scan pass 3: block exclusive scan + offset -> rowstart, cursor ----
__global__ void __launch_bounds__(256) k_scan_fin() {
    __shared__ int sh[256];
    int t = threadIdx.x;
    int i = blockIdx.x * 256 + t;
    int c = (i < NN) ? g_count[i] : 0;
    sh[t] = c;
    __syncthreads();
#pragma unroll
    for (int o = 1; o < 256; o <<= 1) {
        int add = (t >= o) ? sh[t - o] : 0;
        __syncthreads();
        sh[t] += add;
        __syncthreads();
    }
    if (i < NN) {
        int start = sh[t] - c + g_bsumx[blockIdx.x];
        g_rowstart[i] = start;
        g_cursor[i] = start;
    }
}

// ---- K3: exp + CSR bucket-scatter of (src, ex4) ----
__global__ void __launch_bounds__(256) k_csr(const int* __restrict__ ei) {
    int i = blockIdx.x * 256 + threadIdx.x;
    if (i >= EE) return;
    float mx = dec_f(g_maxbits);
    int s = __ldg(ei + i);
    int d = __ldg(ei + EE + i);
    float4 e = *(const float4*)(g_e + (size_t)i * 4);
    float4 ex = make_float4(expf(e.x - mx), expf(e.y - mx),
                            expf(e.z - mx), expf(e.w - mx));
    int pos = atomicAdd(&g_cursor[d], 1);
    g_csr_src[pos] = s;
    *(float4*)(g_csr_ex + (size_t)pos * 4) = ex;
}

// ---- K4: per-node gather-aggregate, fused bias + ELU ----
__global__ void __launch_bounds__(64) k_agg(float* __restrict__ out,
                                            const float* __restrict__ bias) {
    __shared__ int sh_src[64];
    __shared__ float sh_ex[64 * 4];
    int n = blockIdx.x;
    int t = threadIdx.x;
    int h = t >> 4;
    int cnt = g_count[n];
    int start = g_rowstart[n];
    float acc = 0.f, den = 0.f;
    for (int j0 = 0; j0 < cnt; j0 += 64) {
        int m = min(64, cnt - j0);
        __syncthreads();
        if (t < m) {
            sh_src[t] = __ldg(g_csr_src + start + j0 + t);
            ((float4*)sh_ex)[t] = *(const float4*)(g_csr_ex + (size_t)(start + j0 + t) * 4);
        }
        __syncthreads();
        for (int j = 0; j < m; j++) {
            float ex = sh_ex[j * 4 + h];
            den += ex;
            acc += ex * __ldg(g_Wh + (size_t)sh_src[j] * OUTD + t);
        }
    }
    float v = acc / (den + 1e-9f) + __ldg(bias + t);
    out[(size_t)n * OUTD + t] = (v > 0.f) ? v : expm1f(v);
}

extern "C" void kernel_launch(void* const* d_in, const int* in_sizes, int n_in,
                              void* d_out, int out_size) {
    const float* x     = (const float*)d_in[0];
    const int*   ei    = (const int*)d_in[1];
    const float* ea    = (const float*)d_in[2];
    const float* Wn    = (const float*)d_in[3];
    const float* We    = (const float*)d_in[4];
    const float* att_s = (const float*)d_in[5];
    const float* att_d = (const float*)d_in[6];
    const float* bias  = (const float*)d_in[7];
    float* out = (float*)d_out;

    k_init<<<NBLK, 256>>>();
    k_node<<<(NN + 63) / 64, 256>>>(x, Wn, att_s, att_d);
    int ebl = (EE + 255) / 256;
    k_edge_e<<<ebl, 256>>>(ei, ea, We);
    k_scan_bsum<<<NBLK, 256>>>();
    k_scan_top<<<1, 512>>>();
    k_scan_fin<<<NBLK, 256>>>();
    k_csr<<<ebl, 256>>>(ei);
    k_agg<<<NN, 64>>>(out, bias);
}